// round 13
// baseline (speedup 1.0000x reference)
#include <cuda_runtime.h>
#include <cuda_bf16.h>
#include <math.h>
#include <stdint.h>

// Problem constants
#define SEQ   2048
#define BATCH 4
#define EMBED 1024
#define HEADS 16
#define HDIM  64
#define FFN   4096
#define NTOK  (SEQ * BATCH)      // 8192 tokens, row n = b*SEQ + t

// ---------------------------------------------------------------------------
// Scratch (device globals; no allocation allowed)
// ---------------------------------------------------------------------------
__device__ float g_Q [NTOK * EMBED];
__device__ float g_K [NTOK * EMBED];
__device__ float g_V [NTOK * EMBED];
__device__ float g_A [NTOK * EMBED];
__device__ float g_P [NTOK * EMBED];
__device__ float g_X1[NTOK * EMBED];
__device__ float g_H [(size_t)NTOK * FFN];
__device__ float g_Y [NTOK * EMBED];

// ---------------------------------------------------------------------------
// f32x2 packed-FMA helpers (Blackwell FFMA2; PTX sm_100+, non-"a" feature)
// ---------------------------------------------------------------------------
typedef unsigned long long u64;

__device__ __forceinline__ u64 f2pack(float lo, float hi) {
    u64 d;
    asm("mov.b64 %0, {%1, %2};" : "=l"(d) : "f"(lo), "f"(hi));
    return d;
}
__device__ __forceinline__ u64 f2dup(float x) {
    u64 d;
    asm("mov.b64 %0, {%1, %1};" : "=l"(d) : "f"(x));
    return d;
}
__device__ __forceinline__ void f2unpack(u64 d, float& lo, float& hi) {
    asm("mov.b64 {%0, %1}, %2;" : "=f"(lo), "=f"(hi) : "l"(d));
}
__device__ __forceinline__ u64 fma2(u64 a, u64 b, u64 c) {
    u64 d;
    asm("fma.rn.f32x2 %0, %1, %2, %3;" : "=l"(d) : "l"(a), "l"(b), "l"(c));
    return d;
}

// ---------------------------------------------------------------------------
// fp32 SGEMM with packed f32x2 FMA:  C[m,n] = sum_k A[m,k]*W[n,k] + bias[n]
// (optional ReLU). BM=BN=128, BK=16. 256 thr, 8x8 per-thread tile split as
// rows {ty*4..+3, 64+ty*4..+3}, cols {tx*4..+3, 64+tx*4..+3}.
// Double-buffered static smem (transposed A/B tiles, PAD=132, conflict-free).
// ---------------------------------------------------------------------------
#define BM 128
#define BN 128
#define BK 16
#define PAD 132

__global__ __launch_bounds__(256, 2)
void gemm_f32x2_kernel(const float* __restrict__ A, const float* __restrict__ W,
                       const float* __restrict__ bias, float* __restrict__ C,
                       int M, int N, int K, int gatherA, int doRelu)
{
    __shared__ float As[2][BK][PAD];
    __shared__ float Bs[2][BK][PAD];

    const int bm  = blockIdx.y * BM;
    const int bn  = blockIdx.x * BN;
    const int tid = threadIdx.x;
    const int tx  = tid & 15;        // 0..15 -> N direction
    const int ty  = tid >> 4;        // 0..15 -> M direction

    // tile-load mapping: one thread per row half; conflict-free STS
    const int ld_row = tid & 127;            // 0..127
    const int ld_c8  = (tid >> 7) * 8;       // k offset 0 or 8

    const float* a_row_ptr;
    {
        int r = bm + ld_row;
        if (gatherA) {
            int t = r & (SEQ - 1);
            int b = r >> 11;
            a_row_ptr = A + (size_t)t * (BATCH * EMBED) + b * EMBED;
        } else {
            a_row_ptr = A + (size_t)r * K;
        }
    }
    const float* b_row_ptr = W + (size_t)(bn + ld_row) * K;

    u64 acc2[8][4];
#pragma unroll
    for (int i = 0; i < 8; i++)
#pragma unroll
        for (int j = 0; j < 4; j++) acc2[i][j] = 0ULL;

    const int nIter = K / BK;

    float av[8], bv[8];

    // prologue: load tile 0
    {
        float4 x = *(const float4*)(a_row_ptr + ld_c8);
        float4 y = *(const float4*)(a_row_ptr + ld_c8 + 4);
        av[0]=x.x; av[1]=x.y; av[2]=x.z; av[3]=x.w;
        av[4]=y.x; av[5]=y.y; av[6]=y.z; av[7]=y.w;
        x = *(const float4*)(b_row_ptr + ld_c8);
        y = *(const float4*)(b_row_ptr + ld_c8 + 4);
        bv[0]=x.x; bv[1]=x.y; bv[2]=x.z; bv[3]=x.w;
        bv[4]=y.x; bv[5]=y.y; bv[6]=y.z; bv[7]=y.w;
    }
#pragma unroll
    for (int i = 0; i < 8; i++) {
        As[0][ld_c8 + i][ld_row] = av[i];
        Bs[0][ld_c8 + i][ld_row] = bv[i];
    }
    __syncthreads();

    for (int it = 0; it < nIter; it++) {
        const int buf = it & 1;

        const bool hasNext = (it + 1) < nIter;
        if (hasNext) {
            const int k0 = (it + 1) * BK;
            float4 x = *(const float4*)(a_row_ptr + k0 + ld_c8);
            float4 y = *(const float4*)(a_row_ptr + k0 + ld_c8 + 4);
            av[0]=x.x; av[1]=x.y; av[2]=x.z; av[3]=x.w;
            av[4]=y.x; av[5]=y.y; av[6]=y.z; av[7]=y.w;
            x = *(const float4*)(b_row_ptr + k0 + ld_c8);
            y = *(const float4*)(b_row_ptr + k0 + ld_c8 + 4);
            bv[0]=x.x; bv[1]=x.y; bv[2]=x.z; bv[3]=x.w;
            bv[4]=y.x; bv[5]=y.y; bv[6]=y.z; bv[7]=y.w;
        }

        // compute 16 k-steps
#pragma unroll
        for (int k = 0; k < BK; k++) {
            float4 a0 = *(const float4*)&As[buf][k][ty * 4];
            float4 a1 = *(const float4*)&As[buf][k][64 + ty * 4];
            float4 b0 = *(const float4*)&Bs[buf][k][tx * 4];
            float4 b1 = *(const float4*)&Bs[buf][k][64 + tx * 4];

            u64 bp[4];
            bp[0] = f2pack(b0.x, b0.y);
            bp[1] = f2pack(b0.z, b0.w);
            bp[2] = f2pack(b1.x, b1.y);
            bp[3] = f2pack(b1.z, b1.w);

            float am[8] = {a0.x, a0.y, a0.z, a0.w, a1.x, a1.y, a1.z, a1.w};
#pragma unroll
            for (int mi = 0; mi < 8; mi++) {
                u64 ad = f2dup(am[mi]);
#pragma unroll
                for (int bj = 0; bj < 4; bj++)
                    acc2[mi][bj] = fma2(ad, bp[bj], acc2[mi][bj]);
            }
        }

        if (hasNext) {
            const int nb = (it + 1) & 1;
#pragma unroll
            for (int i = 0; i < 8; i++) {
                As[nb][ld_c8 + i][ld_row] = av[i];
                Bs[nb][ld_c8 + i][ld_row] = bv[i];
            }
        }
        __syncthreads();
    }

    // epilogue: bias (+ReLU), vectorized stores
    float4 bias0 = *(const float4*)(bias + bn + tx * 4);
    float4 bias1 = *(const float4*)(bias + bn + 64 + tx * 4);

#pragma unroll
    for (int mi = 0; mi < 8; mi++) {
        const int rrow = bm + ((mi < 4) ? (ty * 4 + mi) : (64 + ty * 4 + mi - 4));
        float c0, c1, c2, c3;
        f2unpack(acc2[mi][0], c0, c1);
        f2unpack(acc2[mi][1], c2, c3);
        float4 o0;
        o0.x = c0 + bias0.x; o0.y = c1 + bias0.y;
        o0.z = c2 + bias0.z; o0.w = c3 + bias0.w;
        f2unpack(acc2[mi][2], c0, c1);
        f2unpack(acc2[mi][3], c2, c3);
        float4 o1;
        o1.x = c0 + bias1.x; o1.y = c1 + bias1.y;
        o1.z = c2 + bias1.z; o1.w = c3 + bias1.w;
        if (doRelu) {
            o0.x = fmaxf(o0.x, 0.f); o0.y = fmaxf(o0.y, 0.f);
            o0.z = fmaxf(o0.z, 0.f); o0.w = fmaxf(o0.w, 0.f);
            o1.x = fmaxf(o1.x, 0.f); o1.y = fmaxf(o1.y, 0.f);
            o1.z = fmaxf(o1.z, 0.f); o1.w = fmaxf(o1.w, 0.f);
        }
        *(float4*)(C + (size_t)rrow * N + bn + tx * 4)      = o0;
        *(float4*)(C + (size_t)rrow * N + bn + 64 + tx * 4) = o1;
    }
}

// ---------------------------------------------------------------------------
// Flash attention (fp32), vectorized smem traffic. (unchanged, measured)
// ---------------------------------------------------------------------------
__global__ __launch_bounds__(256)
void attn_kernel(const float* __restrict__ Q, const float* __restrict__ K,
                 const float* __restrict__ V, const unsigned char* __restrict__ mask,
                 float* __restrict__ O)
{
    __shared__ float Ks[64][64];
    __shared__ float Vs[64][64];
    __shared__ unsigned char ms[64];

    const int bh = blockIdx.y;
    const int b  = bh >> 4;
    const int h  = bh & 15;
    const int tid  = threadIdx.x;
    const int g    = tid >> 2;
    const int lsub = tid & 3;
    const int d0   = lsub * 16;
    const int qrow = blockIdx.x * 64 + g;

    const size_t base = ((size_t)b * SEQ) * EMBED + h * HDIM;

    float q[16];
    {
        const float4* qp = (const float4*)(Q + base + (size_t)qrow * EMBED + d0);
#pragma unroll
        for (int i = 0; i < 4; i++) {
            float4 t = qp[i];
            q[i*4+0] = t.x; q[i*4+1] = t.y; q[i*4+2] = t.z; q[i*4+3] = t.w;
        }
    }

    float m = -1e30f, l = 0.f;
    float o[16];
#pragma unroll
    for (int i = 0; i < 16; i++) o[i] = 0.f;

    const float scale = 0.125f;

    for (int kb = 0; kb < SEQ / 64; kb++) {
#pragma unroll
        for (int i = 0; i < 4; i++) {
            int idx = tid + i * 256;
            int r = idx >> 4, c4 = idx & 15;
            const float4* src = (const float4*)(K + base + (size_t)(kb * 64 + r) * EMBED) + c4;
            ((float4*)&Ks[r][0])[c4] = *src;
            const float4* srcv = (const float4*)(V + base + (size_t)(kb * 64 + r) * EMBED) + c4;
            ((float4*)&Vs[r][0])[c4] = *srcv;
        }
        if (tid < 64) ms[tid] = mask[(size_t)b * SEQ + kb * 64 + tid];
        __syncthreads();

        float s[64];
#pragma unroll
        for (int k = 0; k < 64; k++) {
            const float4* kr = (const float4*)&Ks[k][d0];
            float4 k0 = kr[0], k1 = kr[1], k2 = kr[2], k3 = kr[3];
            s[k] = q[0]*k0.x + q[1]*k0.y + q[2]*k0.z + q[3]*k0.w
                 + q[4]*k1.x + q[5]*k1.y + q[6]*k1.z + q[7]*k1.w
                 + q[8]*k2.x + q[9]*k2.y + q[10]*k2.z + q[11]*k2.w
                 + q[12]*k3.x + q[13]*k3.y + q[14]*k3.z + q[15]*k3.w;
        }
#pragma unroll
        for (int k = 0; k < 64; k++) {
            s[k] += __shfl_xor_sync(0xffffffffu, s[k], 1);
            s[k] += __shfl_xor_sync(0xffffffffu, s[k], 2);
            s[k] *= scale;
            if (ms[k]) s[k] = -1e30f;
        }

        float mloc = -1e30f;
#pragma unroll
        for (int k = 0; k < 64; k++) mloc = fmaxf(mloc, s[k]);
        float mnew = fmaxf(m, mloc);
        float corr = __expf(m - mnew);
        float lsum = 0.f;
#pragma unroll
        for (int k = 0; k < 64; k++) {
            s[k] = __expf(s[k] - mnew);
            lsum += s[k];
        }
        l = l * corr + lsum;
#pragma unroll
        for (int i = 0; i < 16; i++) o[i] *= corr;
#pragma unroll
        for (int k = 0; k < 64; k++) {
            const float p = s[k];
            const float4* vr = (const float4*)&Vs[k][d0];
            float4 v0 = vr[0], v1 = vr[1], v2 = vr[2], v3 = vr[3];
            o[0]  += p * v0.x; o[1]  += p * v0.y; o[2]  += p * v0.z; o[3]  += p * v0.w;
            o[4]  += p * v1.x; o[5]  += p * v1.y; o[6]  += p * v1.z; o[7]  += p * v1.w;
            o[8]  += p * v2.x; o[9]  += p * v2.y; o[10] += p * v2.z; o[11] += p * v2.w;
            o[12] += p * v3.x; o[13] += p * v3.y; o[14] += p * v3.z; o[15] += p * v3.w;
        }
        m = mnew;
        __syncthreads();
    }

    const float inv = 1.f / l;
    float4* op = (float4*)(O + base + (size_t)qrow * EMBED + d0);
#pragma unroll
    for (int i = 0; i < 4; i++) {
        float4 t;
        t.x = o[i*4+0] * inv; t.y = o[i*4+1] * inv;
        t.z = o[i*4+2] * inv; t.w = o[i*4+3] * inv;
        op[i] = t;
    }
}

// ---------------------------------------------------------------------------
// Residual add + LayerNorm (unchanged, measured)
// ---------------------------------------------------------------------------
__global__ __launch_bounds__(256)
void add_ln_kernel(const float* __restrict__ X, const float* __restrict__ R,
                   const float* __restrict__ gam, const float* __restrict__ bet,
                   float* __restrict__ out, int gatherR, int scatterOut)
{
    __shared__ float s_sum[8], s_sq[8];
    __shared__ float s_mu, s_inv;

    const int n   = blockIdx.x;
    const int t   = n & (SEQ - 1);
    const int b   = n >> 11;
    const int tid = threadIdx.x;

    const float* xr = X + (size_t)n * EMBED;
    const float* rr = gatherR ? (R + (size_t)t * (BATCH * EMBED) + b * EMBED)
                              : (R + (size_t)n * EMBED);

    float v[4];
    float sum = 0.f, sq = 0.f;
#pragma unroll
    for (int i = 0; i < 4; i++) {
        int e = tid + i * 256;
        float a = xr[e] + rr[e];
        v[i] = a;
        sum += a;
        sq  += a * a;
    }
#pragma unroll
    for (int off = 16; off > 0; off >>= 1) {
        sum += __shfl_xor_sync(0xffffffffu, sum, off);
        sq  += __shfl_xor_sync(0xffffffffu, sq,  off);
    }
    if ((tid & 31) == 0) { s_sum[tid >> 5] = sum; s_sq[tid >> 5] = sq; }
    __syncthreads();
    if (tid == 0) {
        float ts = 0.f, tq = 0.f;
#pragma unroll
        for (int w = 0; w < 8; w++) { ts += s_sum[w]; tq += s_sq[w]; }
        float mu  = ts / (float)EMBED;
        float var = tq / (float)EMBED - mu * mu;
        s_mu  = mu;
        s_inv = rsqrtf(var + 1e-5f);
    }
    __syncthreads();
    const float mu  = s_mu;
    const float inv = s_inv;
#pragma unroll
    for (int i = 0; i < 4; i++) {
        int e = tid + i * 256;
        float y = (v[i] - mu) * inv * gam[e] + bet[e];
        if (scatterOut)
            out[(size_t)t * (BATCH * EMBED) + b * EMBED + e] = y;
        else
            out[(size_t)n * EMBED + e] = y;
    }
}

// ---------------------------------------------------------------------------
// Launch
// ---------------------------------------------------------------------------
extern "C" void kernel_launch(void* const* d_in, const int* in_sizes, int n_in,
                              void* d_out, int out_size)
{
    const float* state = (const float*)d_in[0];
    const unsigned char* mask = (const unsigned char*)d_in[1];
    const float* q_w  = (const float*)d_in[2];
    const float* q_b  = (const float*)d_in[3];
    const float* k_w  = (const float*)d_in[4];
    const float* k_b  = (const float*)d_in[5];
    const float* v_w  = (const float*)d_in[6];
    const float* v_b  = (const float*)d_in[7];
    const float* o_w  = (const float*)d_in[8];
    const float* o_b  = (const float*)d_in[9];
    const float* ln1g = (const float*)d_in[10];
    const float* ln1b = (const float*)d_in[11];
    const float* f1w  = (const float*)d_in[12];
    const float* f1b  = (const float*)d_in[13];
    const float* f2w  = (const float*)d_in[14];
    const float* f2b  = (const float*)d_in[15];
    const float* ln2g = (const float*)d_in[16];
    const float* ln2b = (const float*)d_in[17];
    float* out = (float*)d_out;

    float *Q, *K, *V, *A, *P, *X1, *H, *Y;
    cudaGetSymbolAddress((void**)&Q,  g_Q);
    cudaGetSymbolAddress((void**)&K,  g_K);
    cudaGetSymbolAddress((void**)&V,  g_V);
    cudaGetSymbolAddress((void**)&A,  g_A);
    cudaGetSymbolAddress((void**)&P,  g_P);
    cudaGetSymbolAddress((void**)&X1, g_X1);
    cudaGetSymbolAddress((void**)&H,  g_H);
    cudaGetSymbolAddress((void**)&Y,  g_Y);

    dim3 blk(256);

    // QKV projections (gather from state layout)
    {
        dim3 grid(EMBED / BN, NTOK / BM);
        gemm_f32x2_kernel<<<grid, blk>>>(state, q_w, q_b, Q, NTOK, EMBED, EMBED, 1, 0);
        gemm_f32x2_kernel<<<grid, blk>>>(state, k_w, k_b, K, NTOK, EMBED, EMBED, 1, 0);
        gemm_f32x2_kernel<<<grid, blk>>>(state, v_w, v_b, V, NTOK, EMBED, EMBED, 1, 0);
    }

    // attention
    {
        dim3 grid(SEQ / 64, BATCH * HEADS);
        attn_kernel<<<grid, blk>>>(Q, K, V, mask, A);
    }

    // output projection
    {
        dim3 grid(EMBED / BN, NTOK / BM);
        gemm_f32x2_kernel<<<grid, blk>>>(A, o_w, o_b, P, NTOK, EMBED, EMBED, 0, 0);
    }

    // residual + LN1
    add_ln_kernel<<<NTOK, blk>>>(P, state, ln1g, ln1b, X1, 1, 0);

    // FFN
    {
        dim3 grid(FFN / BN, NTOK / BM);
        gemm_f32x2_kernel<<<grid, blk>>>(X1, f1w, f1b, H, NTOK, FFN, EMBED, 0, 1);
    }
    {
        dim3 grid(EMBED / BN, NTOK / BM);
        gemm_f32x2_kernel<<<grid, blk>>>(H, f2w, f2b, Y, NTOK, EMBED, FFN, 0, 0);
    }

    // residual + LN2, scatter to (T,B,E)
    add_ln_kernel<<<NTOK, blk>>>(Y, X1, ln2g, ln2b, out, 0, 1);
}